// round 6
// baseline (speedup 1.0000x reference)
#include <cuda_runtime.h>

#define BB 16
#define TT 8192
#define HH 256
#define LCH 64
#define KCH 128           // TT/LCH
#define NG  16            // KCH/8
#define MST 132           // matrix storage: 11 rows x 12 floats (padded)

// Scratch (device globals — no allocation allowed)
__device__ __align__(16) float g_M [(size_t)BB*KCH*MST];  // chunk transfer matrices
__device__ __align__(16) float g_M2[(size_t)BB*NG*MST];   // group matrices
__device__ __align__(16) float g_a0[BB*12];               // ee at t=0 per batch
__device__ float g_num[BB];
__device__ float g_denex[BB];

// C[i][j] = sum_k A[i][k]*B[k][j]; rows padded to 12 floats
__device__ __forceinline__ float mm11(const float* A, const float* Bm, int i, int j){
    float4 r0 = *(const float4*)&A[i*12];
    float4 r1 = *(const float4*)&A[i*12+4];
    float4 r2 = *(const float4*)&A[i*12+8];
    float s =        r0.x*Bm[0*12+j];
    s = fmaf(r0.y, Bm[1*12+j], s);
    s = fmaf(r0.z, Bm[2*12+j], s);
    s = fmaf(r0.w, Bm[3*12+j], s);
    s = fmaf(r1.x, Bm[4*12+j], s);
    s = fmaf(r1.y, Bm[5*12+j], s);
    s = fmaf(r1.z, Bm[6*12+j], s);
    s = fmaf(r1.w, Bm[7*12+j], s);
    s = fmaf(r2.x, Bm[8*12+j], s);
    s = fmaf(r2.y, Bm[9*12+j], s);
    s = fmaf(r2.z, Bm[10*12+j], s);
    return s;
}
__device__ __forceinline__ void storeP(float* C, int i, int j, float v){
    C[i*12+j] = v;
    if (j == 0) C[i*12+11] = 0.f;
}

// ---------------------------------------------------------------------------
// Kernel 0: zero accumulators + output
// ---------------------------------------------------------------------------
__global__ void init_kernel(float* __restrict__ out)
{
    int tid = threadIdx.x;
    if (tid < BB){ g_num[tid] = 0.f; g_denex[tid] = 0.f; }
    if (tid == 0) out[0] = 0.f;
}

// ---------------------------------------------------------------------------
// Kernel 1 (fused): emissions + numerator + chunk transfer-matrix scan.
// Grid (KCH, BB), 128 threads. 2 threads per token (h split), then scan.
// ---------------------------------------------------------------------------
__global__ void __launch_bounds__(128) fused_kernel(
    const float* __restrict__ seq,        // (B,T,4)
    const float* __restrict__ Wenc,       // (4,H)
    const float* __restrict__ benc,       // (H)
    const float* __restrict__ Wemit,      // (H,11)
    const float* __restrict__ bemit,      // (11)
    const float* __restrict__ start_tr,   // (11)
    const float* __restrict__ trans,      // (11,11)
    const float* __restrict__ end_tr,     // (11)
    const int* __restrict__ lengths,      // (B)
    const int* __restrict__ labels)       // (B,T)
{
    __shared__ float4 sEnc[HH];           // (w0,w1,w2,w3) per h
    __shared__ float  sBenc[HH];
    __shared__ float4 sEmit[HH*3];        // Wemit row padded to 12
    __shared__ float  sEem[LCH*12];       // ee[0..10], emmax per step
    __shared__ float  sM[2][MST];
    __shared__ float  sRed[4];
    __shared__ float  sNum, sMx;

    int tid = threadIdx.x;
    int c = blockIdx.x, b = blockIdx.y;
    int t0 = c * LCH;
    int len = lengths[b];

    if (tid == 0){ sNum = 0.f; sMx = 0.f; }

    for (int h = tid; h < HH; h += 128){
        sEnc[h]  = make_float4(Wenc[h], Wenc[HH+h], Wenc[2*HH+h], Wenc[3*HH+h]);
        sBenc[h] = benc[h];
        float e[12];
        #pragma unroll
        for (int q = 0; q < 11; q++) e[q] = Wemit[h*11+q];
        e[11] = 0.f;
        sEmit[h*3+0] = make_float4(e[0], e[1], e[2],  e[3]);
        sEmit[h*3+1] = make_float4(e[4], e[5], e[6],  e[7]);
        sEmit[h*3+2] = make_float4(e[8], e[9], e[10], e[11]);
    }
    __syncthreads();

    // ---- phase 1: emissions (2 threads/token, h halves) ----
    {
        int seg = tid & 1;           // which half of H
        int tp  = tid >> 1;          // token within chunk
        int t   = t0 + tp;
        float4 x = ((const float4*)seq)[(size_t)b*TT + t];

        float acc[11];
        #pragma unroll
        for (int q = 0; q < 11; q++) acc[q] = seg ? 0.f : bemit[q];

        int h0 = seg * 128;
        #pragma unroll 4
        for (int h = h0; h < h0 + 128; h++){
            float4 w = sEnc[h];
            float hd = fmaxf(fmaf(x.x,w.x,fmaf(x.y,w.y,fmaf(x.z,w.z,fmaf(x.w,w.w,sBenc[h])))), 0.f);
            float4 e0 = sEmit[h*3+0], e1 = sEmit[h*3+1], e2 = sEmit[h*3+2];
            acc[0]  = fmaf(hd, e0.x, acc[0]);  acc[1]  = fmaf(hd, e0.y, acc[1]);
            acc[2]  = fmaf(hd, e0.z, acc[2]);  acc[3]  = fmaf(hd, e0.w, acc[3]);
            acc[4]  = fmaf(hd, e1.x, acc[4]);  acc[5]  = fmaf(hd, e1.y, acc[5]);
            acc[6]  = fmaf(hd, e1.z, acc[6]);  acc[7]  = fmaf(hd, e1.w, acc[7]);
            acc[8]  = fmaf(hd, e2.x, acc[8]);  acc[9]  = fmaf(hd, e2.y, acc[9]);
            acc[10] = fmaf(hd, e2.z, acc[10]);
        }
        #pragma unroll
        for (int q = 0; q < 11; q++) acc[q] += __shfl_xor_sync(0xffffffffu, acc[q], 1);

        if (seg == 0){
            float mx = acc[0];
            #pragma unroll
            for (int q = 1; q < 11; q++) mx = fmaxf(mx, acc[q]);
            float ee[11];
            #pragma unroll
            for (int q = 0; q < 11; q++) ee[q] = __expf(acc[q] - mx);
            float4* d4 = (float4*)&sEem[tp*12];
            d4[0] = make_float4(ee[0],ee[1],ee[2],ee[3]);
            d4[1] = make_float4(ee[4],ee[5],ee[6],ee[7]);
            d4[2] = make_float4(ee[8],ee[9],ee[10],mx);

            float numc = 0.f, mxs = 0.f;
            if (t < len) mxs = mx;

            int lab = labels[(size_t)b*TT + t];
            int tag = (lab == -100) ? 0 : lab;
            float emt = acc[0];
            #pragma unroll
            for (int q = 1; q < 11; q++) if (tag == q) emt = acc[q];

            if (t == 0){
                numc += start_tr[tag] + emt;
                float4* g4 = (float4*)&g_a0[b*12];
                g4[0] = make_float4(ee[0],ee[1],ee[2],ee[3]);
                g4[1] = make_float4(ee[4],ee[5],ee[6],ee[7]);
                g4[2] = make_float4(ee[8],ee[9],ee[10],0.f);
            } else if (t < len){
                int labp = labels[(size_t)b*TT + t - 1];
                int tagp = (labp == -100) ? 0 : labp;
                numc += trans[tagp*11 + tag] + emt;
            }
            if (t == len - 1) numc += end_tr[tag];

            if (numc != 0.f) atomicAdd(&sNum, numc);
            if (mxs  != 0.f) atomicAdd(&sMx, mxs);
        }
    }
    __syncthreads();

    // ---- phase 2: 64-step transfer-matrix scan ----
    int i = tid / 11, j = tid - i*11;
    bool act = tid < 121;
    float Tc[11];
    #pragma unroll
    for (int k = 0; k < 11; k++) Tc[k] = act ? __expf(trans[k*11 + j]) : 0.f;

    float v = (act && i == j) ? 1.f : 0.f;
    if (act){
        sM[0][i*12 + j] = v;
        if (j == 0){ sM[0][i*12 + 11] = 0.f; sM[1][i*12 + 11] = 0.f; }
    }
    int e_tot = 0;
    __syncthreads();

    int cur = 0;
    for (int s = 0; s < LCH; s++){
        int t = t0 + s;
        bool valid = (t >= 1) && (t < len);
        if (act && valid){
            const float4* row = (const float4*)&sM[cur][i*12];
            float4 r0 = row[0], r1 = row[1], r2 = row[2];
            float sum =      r0.x*Tc[0];
            sum = fmaf(r0.y, Tc[1], sum);
            sum = fmaf(r0.z, Tc[2], sum);
            sum = fmaf(r0.w, Tc[3], sum);
            sum = fmaf(r1.x, Tc[4], sum);
            sum = fmaf(r1.y, Tc[5], sum);
            sum = fmaf(r1.z, Tc[6], sum);
            sum = fmaf(r1.w, Tc[7], sum);
            sum = fmaf(r2.x, Tc[8], sum);
            sum = fmaf(r2.y, Tc[9], sum);
            sum = fmaf(r2.z, Tc[10], sum);
            v = sum * sEem[s*12 + j];
        }
        if ((s & 7) == 7){
            float m2 = v;
            #pragma unroll
            for (int o = 16; o > 0; o >>= 1) m2 = fmaxf(m2, __shfl_xor_sync(0xffffffffu, m2, o));
            if ((tid & 31) == 0) sRed[tid >> 5] = m2;
            __syncthreads();
            float mxv = fmaxf(fmaxf(sRed[0], sRed[1]), fmaxf(sRed[2], sRed[3]));
            int e = 0;
            frexpf(mxv, &e);
            v *= exp2f((float)(-e));
            e_tot += e;
        }
        if (act) sM[cur ^ 1][i*12 + j] = v;
        __syncthreads();
        cur ^= 1;
    }

    if (act){
        size_t base = ((size_t)(b*KCH + c)) * MST;
        g_M[base + i*12 + j] = v;
        if (j == 0) g_M[base + i*12 + 11] = 0.f;
    }
    if (tid == 0){
        atomicAdd(&g_num[b], sNum);
        atomicAdd(&g_denex[b], sMx + 0.6931471805599453f * (float)e_tot);
    }
}

// ---------------------------------------------------------------------------
// Kernel 2: combine 8 chunk matrices -> 1 group matrix (3-level tree).
// Grid (NG, BB), 512 threads.
// ---------------------------------------------------------------------------
__global__ void __launch_bounds__(512) combine8_kernel()
{
    __shared__ float sIn[8*MST];
    __shared__ float sL1[4*MST];
    __shared__ float sL2[2*MST];
    __shared__ float sRed[16];

    int tid = threadIdx.x;
    int g = blockIdx.x, b = blockIdx.y;

    const float4* src = (const float4*)&g_M[((size_t)(b*KCH + g*8)) * MST];
    for (int q = tid; q < 8*MST/4; q += 512) ((float4*)sIn)[q] = src[q];
    __syncthreads();

    int grp = tid >> 7, st = tid & 127;
    int i = st / 11, j = st - i*11;
    bool act = st < 121;

    if (act)
        storeP(&sL1[grp*MST], i, j, mm11(&sIn[(2*grp)*MST], &sIn[(2*grp+1)*MST], i, j));
    __syncthreads();
    if (grp < 2 && act)
        storeP(&sL2[grp*MST], i, j, mm11(&sL1[(2*grp)*MST], &sL1[(2*grp+1)*MST], i, j));
    __syncthreads();

    float v = 0.f;
    if (grp == 0 && act) v = mm11(&sL2[0], &sL2[MST], i, j);

    float m2 = v;
    #pragma unroll
    for (int o = 16; o > 0; o >>= 1) m2 = fmaxf(m2, __shfl_xor_sync(0xffffffffu, m2, o));
    if ((tid & 31) == 0) sRed[tid >> 5] = m2;
    __syncthreads();
    float mxv = sRed[0];
    #pragma unroll
    for (int q = 1; q < 16; q++) mxv = fmaxf(mxv, sRed[q]);
    int e = 0;
    frexpf(mxv, &e);
    if (grp == 0 && act){
        size_t base = ((size_t)(b*NG + g)) * MST;
        g_M2[base + i*12 + j] = v * exp2f((float)(-e));
        if (j == 0) g_M2[base + i*12 + 11] = 0.f;
    }
    if (tid == 0) atomicAdd(&g_denex[b], 0.6931471805599453f * (float)e);
}

// ---------------------------------------------------------------------------
// Kernel 3: per-batch product of NG group matrices (4-level tree) + loss.
// Grid BB, 512 threads.
// ---------------------------------------------------------------------------
__global__ void __launch_bounds__(512) final_kernel(
    const float* __restrict__ start_tr,
    const float* __restrict__ end_tr,
    float* __restrict__ out)
{
    __shared__ float sIn[16*MST];
    __shared__ float sL1[8*MST];
    __shared__ float sL2[4*MST];
    __shared__ float sL3[2*MST];
    __shared__ float sP[MST];

    int tid = threadIdx.x;
    int b = blockIdx.x;

    const float4* src = (const float4*)&g_M2[((size_t)b*NG) * MST];
    for (int q = tid; q < 16*MST/4; q += 512) ((float4*)sIn)[q] = src[q];
    __syncthreads();

    int grp = tid >> 7, st = tid & 127;
    int i = st / 11, j = st - i*11;
    bool act = st < 121;

    if (act){
        #pragma unroll
        for (int m = grp; m < 8; m += 4)
            storeP(&sL1[m*MST], i, j, mm11(&sIn[(2*m)*MST], &sIn[(2*m+1)*MST], i, j));
    }
    __syncthreads();
    if (act)
        storeP(&sL2[grp*MST], i, j, mm11(&sL1[(2*grp)*MST], &sL1[(2*grp+1)*MST], i, j));
    __syncthreads();
    if (grp < 2 && act)
        storeP(&sL3[grp*MST], i, j, mm11(&sL2[(2*grp)*MST], &sL2[(2*grp+1)*MST], i, j));
    __syncthreads();
    if (grp == 0 && act)
        storeP(sP, i, j, mm11(&sL3[0], &sL3[MST], i, j));
    __syncthreads();

    if (tid < 32){
        bool a11 = tid < 11;
        float p0 = a11 ? __expf(start_tr[tid]) * g_a0[b*12 + tid] : 0.f;
        float pf = 0.f;
        #pragma unroll
        for (int k = 0; k < 11; k++){
            float pkv = __shfl_sync(0xffffffffu, p0, k);
            pf = fmaf(pkv, a11 ? sP[k*12 + tid] : 0.f, pf);
        }
        float vv = a11 ? pf * __expf(end_tr[tid]) : 0.f;
        #pragma unroll
        for (int o = 16; o > 0; o >>= 1) vv += __shfl_xor_sync(0xffffffffu, vv, o);
        if (tid == 0){
            float den = logf(vv) + g_denex[b];
            atomicAdd(out, (den - g_num[b]) * (1.0f / (float)BB));
        }
    }
}

// ---------------------------------------------------------------------------
// Launch
// ---------------------------------------------------------------------------
extern "C" void kernel_launch(void* const* d_in, const int* in_sizes, int n_in,
                              void* d_out, int out_size)
{
    const float* seq      = (const float*)d_in[0];
    const float* Wenc     = (const float*)d_in[1];
    const float* benc     = (const float*)d_in[2];
    const float* Wemit    = (const float*)d_in[3];
    const float* bemit    = (const float*)d_in[4];
    const float* start_tr = (const float*)d_in[5];
    const float* trans    = (const float*)d_in[6];
    const float* end_tr   = (const float*)d_in[7];
    const int* lengths    = (const int*)d_in[8];
    const int* labels     = (const int*)d_in[9];
    float* out = (float*)d_out;

    init_kernel<<<1, 128>>>(out);
    fused_kernel<<<dim3(KCH, BB), 128>>>(seq, Wenc, benc, Wemit, bemit,
                                         start_tr, trans, end_tr, lengths, labels);
    combine8_kernel<<<dim3(NG, BB), 512>>>();
    final_kernel<<<BB, 512>>>(start_tr, end_tr, out);
}

// round 7
// speedup vs baseline: 1.2179x; 1.2179x over previous
#include <cuda_runtime.h>

#define BB 16
#define TT 8192
#define HH 256
#define LCH 64
#define KCH 128           // TT/LCH
#define NG  16            // KCH/8
#define MST 132           // matrix storage: 11 rows x 12 floats (padded)

// Scratch (device globals — no allocation allowed)
__device__ __align__(16) float g_eem[(size_t)BB*TT*12];   // per token: ee[0..10], emmax
__device__ __align__(16) float g_M [(size_t)BB*KCH*MST];  // chunk transfer matrices
__device__ __align__(16) float g_M2[(size_t)BB*NG*MST];   // group matrices
__device__ __align__(16) float g_a0[BB*12];               // ee at t=0 per batch
__device__ float g_T[121];                                 // exp(trans)
__device__ float g_num[BB];
__device__ float g_denex[BB];

// C[i][j] = sum_k A[i][k]*B[k][j]; rows padded to 12 floats
__device__ __forceinline__ float mm11(const float* A, const float* Bm, int i, int j){
    float4 r0 = *(const float4*)&A[i*12];
    float4 r1 = *(const float4*)&A[i*12+4];
    float4 r2 = *(const float4*)&A[i*12+8];
    float s =        r0.x*Bm[0*12+j];
    s = fmaf(r0.y, Bm[1*12+j], s);
    s = fmaf(r0.z, Bm[2*12+j], s);
    s = fmaf(r0.w, Bm[3*12+j], s);
    s = fmaf(r1.x, Bm[4*12+j], s);
    s = fmaf(r1.y, Bm[5*12+j], s);
    s = fmaf(r1.z, Bm[6*12+j], s);
    s = fmaf(r1.w, Bm[7*12+j], s);
    s = fmaf(r2.x, Bm[8*12+j], s);
    s = fmaf(r2.y, Bm[9*12+j], s);
    s = fmaf(r2.z, Bm[10*12+j], s);
    return s;
}
__device__ __forceinline__ void storeP(float* C, int i, int j, float v){
    C[i*12+j] = v;
    if (j == 0) C[i*12+11] = 0.f;
}

// ---------------------------------------------------------------------------
// Kernel 0: init accumulators + exp(trans)
// ---------------------------------------------------------------------------
__global__ void init_kernel(const float* __restrict__ trans, float* __restrict__ out)
{
    int tid = threadIdx.x;
    if (tid < 121) g_T[tid] = __expf(trans[tid]);
    if (tid < BB){ g_num[tid] = 0.f; g_denex[tid] = 0.f; }
    if (tid == 0) out[0] = 0.f;
}

// ---------------------------------------------------------------------------
// Kernel 1: emissions + numerator (round-3 proven version; adds g_a0 + emmax(t=0))
// Grid (TT/128, BB), 128 threads; 1 thread per token.
// ---------------------------------------------------------------------------
__global__ void __launch_bounds__(128) em_kernel(
    const float* __restrict__ seq,        // (B,T,4)
    const float* __restrict__ Wenc,       // (4,H)
    const float* __restrict__ benc,       // (H)
    const float* __restrict__ Wemit,      // (H,11)
    const float* __restrict__ bemit,      // (11)
    const float* __restrict__ start_tr,   // (11)
    const float* __restrict__ trans,      // (11,11)
    const float* __restrict__ end_tr,     // (11)
    const int* __restrict__ lengths,      // (B) int32
    const int* __restrict__ labels)       // (B,T) int32
{
    __shared__ float4 sEnc[HH];
    __shared__ float  sBenc[HH];
    __shared__ float4 sEmit[HH*3];
    __shared__ float  sRed[4];

    int tid = threadIdx.x;
    int b = blockIdx.y;
    int t = blockIdx.x * 128 + tid;

    for (int i = tid; i < HH; i += 128) {
        sEnc[i]  = make_float4(Wenc[i], Wenc[HH+i], Wenc[2*HH+i], Wenc[3*HH+i]);
        sBenc[i] = benc[i];
        float e[12];
        #pragma unroll
        for (int c = 0; c < 11; c++) e[c] = Wemit[i*11 + c];
        e[11] = 0.f;
        sEmit[i*3+0] = make_float4(e[0], e[1], e[2],  e[3]);
        sEmit[i*3+1] = make_float4(e[4], e[5], e[6],  e[7]);
        sEmit[i*3+2] = make_float4(e[8], e[9], e[10], e[11]);
    }
    __syncthreads();

    float4 x = reinterpret_cast<const float4*>(seq)[(size_t)b*TT + t];

    float acc[11];
    #pragma unroll
    for (int c = 0; c < 11; c++) acc[c] = bemit[c];

    #pragma unroll 8
    for (int h = 0; h < HH; h++) {
        float4 w = sEnc[h];
        float hd = fmaxf(fmaf(x.x, w.x, fmaf(x.y, w.y, fmaf(x.z, w.z, fmaf(x.w, w.w, sBenc[h])))), 0.f);
        float4 e0 = sEmit[h*3+0], e1 = sEmit[h*3+1], e2 = sEmit[h*3+2];
        acc[0]  = fmaf(hd, e0.x, acc[0]);  acc[1]  = fmaf(hd, e0.y, acc[1]);
        acc[2]  = fmaf(hd, e0.z, acc[2]);  acc[3]  = fmaf(hd, e0.w, acc[3]);
        acc[4]  = fmaf(hd, e1.x, acc[4]);  acc[5]  = fmaf(hd, e1.y, acc[5]);
        acc[6]  = fmaf(hd, e1.z, acc[6]);  acc[7]  = fmaf(hd, e1.w, acc[7]);
        acc[8]  = fmaf(hd, e2.x, acc[8]);  acc[9]  = fmaf(hd, e2.y, acc[9]);
        acc[10] = fmaf(hd, e2.z, acc[10]);
    }

    float mx = acc[0];
    #pragma unroll
    for (int c = 1; c < 11; c++) mx = fmaxf(mx, acc[c]);
    float ee[12];
    #pragma unroll
    for (int c = 0; c < 11; c++) ee[c] = __expf(acc[c] - mx);
    ee[11] = mx;
    float4* dst = reinterpret_cast<float4*>(&g_eem[((size_t)b*TT + t) * 12]);
    dst[0] = make_float4(ee[0], ee[1], ee[2],  ee[3]);
    dst[1] = make_float4(ee[4], ee[5], ee[6],  ee[7]);
    dst[2] = make_float4(ee[8], ee[9], ee[10], ee[11]);

    // numerator contribution
    int len = lengths[b];
    int lab = labels[(size_t)b*TT + t];
    int tag = (lab == -100) ? 0 : lab;
    float emtag = acc[0];
    #pragma unroll
    for (int c = 1; c < 11; c++) if (tag == c) emtag = acc[c];

    float contrib = 0.f;
    if (t == 0) {
        contrib = start_tr[tag] + emtag;
        float4* g4 = (float4*)&g_a0[b*12];
        g4[0] = make_float4(ee[0],ee[1],ee[2],ee[3]);
        g4[1] = make_float4(ee[4],ee[5],ee[6],ee[7]);
        g4[2] = make_float4(ee[8],ee[9],ee[10],0.f);
        atomicAdd(&g_denex[b], mx);      // emmax at t=0
    } else if (t < len) {
        int labp = labels[(size_t)b*TT + t - 1];
        int tagp = (labp == -100) ? 0 : labp;
        contrib = trans[tagp*11 + tag] + emtag;
    }
    if (t == len - 1) contrib += end_tr[tag];

    #pragma unroll
    for (int o = 16; o > 0; o >>= 1) contrib += __shfl_xor_sync(0xffffffffu, contrib, o);
    if ((tid & 31) == 0) sRed[tid >> 5] = contrib;
    __syncthreads();
    if (tid == 0) atomicAdd(&g_num[b], sRed[0] + sRed[1] + sRed[2] + sRed[3]);
}

// ---------------------------------------------------------------------------
// Kernel 2: per-chunk transfer matrix by BINARY TREE (depth 6, ~13 barriers).
// Grid (KCH, BB), 512 threads = 4 matmul units of 128 (121 active).
// A_s = T*diag(ee_s); invalid steps are identity. L1 fuses pairs from T+ee.
// L3..L6 products pow2-normalized; exponents accumulate into g_denex.
// ---------------------------------------------------------------------------
__global__ void __launch_bounds__(512) chunktree_kernel(const int* __restrict__ lengths)
{
    __shared__ float sT[MST];
    __shared__ float sEem[LCH*12];
    __shared__ float sP1[32*MST];
    __shared__ float sP2[16*MST];
    __shared__ float sP3[8*MST];
    __shared__ float sP4[4*MST];
    __shared__ float sP5[2*MST];
    __shared__ float sRedM[16];
    __shared__ float sMx;
    __shared__ int   sExp;

    int tid = threadIdx.x;
    int c = blockIdx.x, b = blockIdx.y;
    int t0 = c * LCH;
    int len = lengths[b];

    if (tid == 0){ sMx = 0.f; sExp = 0; }
    if (tid < 121){
        int ki = tid / 11, kj = tid - ki*11;
        sT[ki*12 + kj] = g_T[tid];
        if (kj == 0) sT[ki*12 + 11] = 0.f;
    }
    {
        const float4* src = (const float4*)&g_eem[((size_t)b*TT + t0) * 12];
        for (int q = tid; q < LCH*3; q += 512) ((float4*)sEem)[q] = src[q];
    }
    __syncthreads();

    // emmax sum over valid steps (t>=1 && t<len)
    if (tid < 64){
        int t = t0 + tid;
        float m = (t >= 1 && t < len) ? sEem[tid*12 + 11] : 0.f;
        #pragma unroll
        for (int o = 16; o > 0; o >>= 1) m += __shfl_xor_sync(0xffffffffu, m, o);
        if ((tid & 31) == 0) atomicAdd(&sMx, m);
    }

    int unit = tid >> 7, st = tid & 127;
    int i = st / 11, j = st - i*11;
    bool act = st < 121;
    int wiu = st >> 5;    // warp within unit

    // ---- L1: 32 pair products, fused from T and ee (rounds independent) ----
    #pragma unroll
    for (int r = 0; r < 8; r++){
        int p = r*4 + unit;          // product 0..31 covers tokens 2p, 2p+1
        int ta = t0 + 2*p, tb = ta + 1;
        bool v1 = (ta >= 1 && ta < len), v2 = (tb >= 1 && tb < len);
        if (act){
            float val;
            if (v1 && v2){
                const float* e1 = &sEem[(2*p)*12];
                float s = 0.f;
                #pragma unroll
                for (int k = 0; k < 11; k++)
                    s = fmaf(sT[i*12+k]*e1[k], sT[k*12+j], s);
                val = s * sEem[(2*p+1)*12 + j];
            } else if (v2){
                val = sT[i*12+j] * sEem[(2*p+1)*12 + j];
            } else if (v1){
                val = sT[i*12+j] * sEem[(2*p)*12 + j];
            } else {
                val = (i == j) ? 1.f : 0.f;
            }
            storeP(&sP1[p*MST], i, j, val);
        }
    }
    __syncthreads();

    // ---- L2: 16 products (unnormalized; bounded) ----
    #pragma unroll
    for (int r = 0; r < 4; r++){
        int q = r*4 + unit;
        if (act) storeP(&sP2[q*MST], i, j, mm11(&sP1[(2*q)*MST], &sP1[(2*q+1)*MST], i, j));
    }
    __syncthreads();

    // ---- L3: 8 products, normalized ----
    #pragma unroll
    for (int r = 0; r < 2; r++){
        int q = r*4 + unit;
        float v = act ? mm11(&sP2[(2*q)*MST], &sP2[(2*q+1)*MST], i, j) : 0.f;
        float m = v;
        #pragma unroll
        for (int o = 16; o > 0; o >>= 1) m = fmaxf(m, __shfl_xor_sync(0xffffffffu, m, o));
        if ((st & 31) == 0) sRedM[unit*4 + wiu] = m;
        __syncthreads();
        float mxv = fmaxf(fmaxf(sRedM[unit*4], sRedM[unit*4+1]), fmaxf(sRedM[unit*4+2], sRedM[unit*4+3]));
        int e = 0; frexpf(mxv, &e);
        if (act) storeP(&sP3[q*MST], i, j, v * exp2f((float)(-e)));
        if (st == 0) atomicAdd(&sExp, e);
        __syncthreads();
    }

    // ---- L4: 4 products, normalized ----
    {
        int q = unit;
        float v = act ? mm11(&sP3[(2*q)*MST], &sP3[(2*q+1)*MST], i, j) : 0.f;
        float m = v;
        #pragma unroll
        for (int o = 16; o > 0; o >>= 1) m = fmaxf(m, __shfl_xor_sync(0xffffffffu, m, o));
        if ((st & 31) == 0) sRedM[unit*4 + wiu] = m;
        __syncthreads();
        float mxv = fmaxf(fmaxf(sRedM[unit*4], sRedM[unit*4+1]), fmaxf(sRedM[unit*4+2], sRedM[unit*4+3]));
        int e = 0; frexpf(mxv, &e);
        if (act) storeP(&sP4[q*MST], i, j, v * exp2f((float)(-e)));
        if (st == 0) atomicAdd(&sExp, e);
        __syncthreads();
    }

    // ---- L5: 2 products (units 0,1), normalized ----
    {
        bool run = unit < 2;
        float v = (run && act) ? mm11(&sP4[(2*unit)*MST], &sP4[(2*unit+1)*MST], i, j) : 0.f;
        float m = v;
        #pragma unroll
        for (int o = 16; o > 0; o >>= 1) m = fmaxf(m, __shfl_xor_sync(0xffffffffu, m, o));
        if ((st & 31) == 0) sRedM[unit*4 + wiu] = m;
        __syncthreads();
        float mxv = fmaxf(fmaxf(sRedM[unit*4], sRedM[unit*4+1]), fmaxf(sRedM[unit*4+2], sRedM[unit*4+3]));
        int e = 0; frexpf(mxv, &e);
        if (run && act) storeP(&sP5[unit*MST], i, j, v * exp2f((float)(-e)));
        if (run && st == 0) atomicAdd(&sExp, e);
        __syncthreads();
    }

    // ---- L6: final product (unit 0), normalized, to global ----
    {
        bool run = unit == 0;
        float v = (run && act) ? mm11(&sP5[0], &sP5[MST], i, j) : 0.f;
        float m = v;
        #pragma unroll
        for (int o = 16; o > 0; o >>= 1) m = fmaxf(m, __shfl_xor_sync(0xffffffffu, m, o));
        if ((st & 31) == 0) sRedM[unit*4 + wiu] = m;
        __syncthreads();
        float mxv = fmaxf(fmaxf(sRedM[0], sRedM[1]), fmaxf(sRedM[2], sRedM[3]));
        int e = 0; frexpf(mxv, &e);
        if (run && st == 0) atomicAdd(&sExp, e);
        if (run && act){
            size_t base = ((size_t)(b*KCH + c)) * MST;
            g_M[base + i*12 + j] = v * exp2f((float)(-e));
            if (j == 0) g_M[base + i*12 + 11] = 0.f;
        }
    }
    __syncthreads();
    if (tid == 0)
        atomicAdd(&g_denex[b], sMx + 0.6931471805599453f * (float)sExp);
}

// ---------------------------------------------------------------------------
// Kernel 3: combine 8 chunk matrices -> 1 group matrix (3-level tree).
// Grid (NG, BB), 512 threads.
// ---------------------------------------------------------------------------
__global__ void __launch_bounds__(512) combine8_kernel()
{
    __shared__ float sIn[8*MST];
    __shared__ float sL1[4*MST];
    __shared__ float sL2[2*MST];
    __shared__ float sRed[16];

    int tid = threadIdx.x;
    int g = blockIdx.x, b = blockIdx.y;

    const float4* src = (const float4*)&g_M[((size_t)(b*KCH + g*8)) * MST];
    for (int q = tid; q < 8*MST/4; q += 512) ((float4*)sIn)[q] = src[q];
    __syncthreads();

    int grp = tid >> 7, st = tid & 127;
    int i = st / 11, j = st - i*11;
    bool act = st < 121;

    if (act)
        storeP(&sL1[grp*MST], i, j, mm11(&sIn[(2*grp)*MST], &sIn[(2*grp+1)*MST], i, j));
    __syncthreads();
    if (grp < 2 && act)
        storeP(&sL2[grp*MST], i, j, mm11(&sL1[(2*grp)*MST], &sL1[(2*grp+1)*MST], i, j));
    __syncthreads();

    float v = 0.f;
    if (grp == 0 && act) v = mm11(&sL2[0], &sL2[MST], i, j);

    float m2 = v;
    #pragma unroll
    for (int o = 16; o > 0; o >>= 1) m2 = fmaxf(m2, __shfl_xor_sync(0xffffffffu, m2, o));
    if ((tid & 31) == 0) sRed[tid >> 5] = m2;
    __syncthreads();
    float mxv = sRed[0];
    #pragma unroll
    for (int q = 1; q < 16; q++) mxv = fmaxf(mxv, sRed[q]);
    int e = 0;
    frexpf(mxv, &e);
    if (grp == 0 && act){
        size_t base = ((size_t)(b*NG + g)) * MST;
        g_M2[base + i*12 + j] = v * exp2f((float)(-e));
        if (j == 0) g_M2[base + i*12 + 11] = 0.f;
    }
    if (tid == 0) atomicAdd(&g_denex[b], 0.6931471805599453f * (float)e);
}

// ---------------------------------------------------------------------------
// Kernel 4: per-batch product of NG group matrices (4-level tree) + loss.
// Grid BB, 512 threads.
// ---------------------------------------------------------------------------
__global__ void __launch_bounds__(512) final_kernel(
    const float* __restrict__ start_tr,
    const float* __restrict__ end_tr,
    float* __restrict__ out)
{
    __shared__ float sIn[16*MST];
    __shared__ float sL1[8*MST];
    __shared__ float sL2[4*MST];
    __shared__ float sL3[2*MST];
    __shared__ float sP[MST];

    int tid = threadIdx.x;
    int b = blockIdx.x;

    const float4* src = (const float4*)&g_M2[((size_t)b*NG) * MST];
    for (int q = tid; q < 16*MST/4; q += 512) ((float4*)sIn)[q] = src[q];
    __syncthreads();

    int grp = tid >> 7, st = tid & 127;
    int i = st / 11, j = st - i*11;
    bool act = st < 121;

    if (act){
        #pragma unroll
        for (int m = grp; m < 8; m += 4)
            storeP(&sL1[m*MST], i, j, mm11(&sIn[(2*m)*MST], &sIn[(2*m+1)*MST], i, j));
    }
    __syncthreads();
    if (act)
        storeP(&sL2[grp*MST], i, j, mm11(&sL1[(2*grp)*MST], &sL1[(2*grp+1)*MST], i, j));
    __syncthreads();
    if (grp < 2 && act)
        storeP(&sL3[grp*MST], i, j, mm11(&sL2[(2*grp)*MST], &sL2[(2*grp+1)*MST], i, j));
    __syncthreads();
    if (grp == 0 && act)
        storeP(sP, i, j, mm11(&sL3[0], &sL3[MST], i, j));
    __syncthreads();

    if (tid < 32){
        bool a11 = tid < 11;
        float p0 = a11 ? __expf(start_tr[tid]) * g_a0[b*12 + tid] : 0.f;
        float pf = 0.f;
        #pragma unroll
        for (int k = 0; k < 11; k++){
            float pkv = __shfl_sync(0xffffffffu, p0, k);
            pf = fmaf(pkv, a11 ? sP[k*12 + tid] : 0.f, pf);
        }
        float vv = a11 ? pf * __expf(end_tr[tid]) : 0.f;
        #pragma unroll
        for (int o = 16; o > 0; o >>= 1) vv += __shfl_xor_sync(0xffffffffu, vv, o);
        if (tid == 0){
            float den = logf(vv) + g_denex[b];
            atomicAdd(out, (den - g_num[b]) * (1.0f / (float)BB));
        }
    }
}

// ---------------------------------------------------------------------------
// Launch
// ---------------------------------------------------------------------------
extern "C" void kernel_launch(void* const* d_in, const int* in_sizes, int n_in,
                              void* d_out, int out_size)
{
    const float* seq      = (const float*)d_in[0];
    const float* Wenc     = (const float*)d_in[1];
    const float* benc     = (const float*)d_in[2];
    const float* Wemit    = (const float*)d_in[3];
    const float* bemit    = (const float*)d_in[4];
    const float* start_tr = (const float*)d_in[5];
    const float* trans    = (const float*)d_in[6];
    const float* end_tr   = (const float*)d_in[7];
    const int* lengths    = (const int*)d_in[8];
    const int* labels     = (const int*)d_in[9];
    float* out = (float*)d_out;

    init_kernel<<<1, 128>>>(trans, out);
    em_kernel<<<dim3(TT/128, BB), 128>>>(seq, Wenc, benc, Wemit, bemit,
                                         start_tr, trans, end_tr, lengths, labels);
    chunktree_kernel<<<dim3(KCH, BB), 512>>>(lengths);
    combine8_kernel<<<dim3(NG, BB), 512>>>();
    final_kernel<<<BB, 512>>>(start_tr, end_tr, out);
}

// round 9
// speedup vs baseline: 1.4351x; 1.1783x over previous
#include <cuda_runtime.h>

#define BB 16
#define TT 8192
#define HH 256
#define LCH 64
#define KCH 128           // TT/LCH
#define MST 132           // matrix storage: 11 rows x 12 floats (padded)
#define NBLK 64           // em blocks per batch (TT/128)

// Scratch (device globals — no allocation allowed)
__device__ __align__(16) float g_eem[(size_t)BB*TT*12];   // per token: ee[0..10], emmax
__device__ __align__(16) float g_M [(size_t)BB*KCH*MST];  // chunk transfer matrices
__device__ __align__(16) float g_a0[BB*12];               // ee at t=0 per batch
__device__ float g_numpart[BB*NBLK];                       // per-em-block numerator partials
__device__ float g_denpart[BB*NBLK];                       // per-em-block emmax-sum partials
__device__ int   g_exps[BB*KCH];                           // per-chunk pow2 exponents

// C[i][j] = sum_k A[i][k]*B[k][j]; rows padded to 12 floats
__device__ __forceinline__ float mm11(const float* A, const float* Bm, int i, int j){
    float4 r0 = *(const float4*)&A[i*12];
    float4 r1 = *(const float4*)&A[i*12+4];
    float4 r2 = *(const float4*)&A[i*12+8];
    float s =        r0.x*Bm[0*12+j];
    s = fmaf(r0.y, Bm[1*12+j], s);
    s = fmaf(r0.z, Bm[2*12+j], s);
    s = fmaf(r0.w, Bm[3*12+j], s);
    s = fmaf(r1.x, Bm[4*12+j], s);
    s = fmaf(r1.y, Bm[5*12+j], s);
    s = fmaf(r1.z, Bm[6*12+j], s);
    s = fmaf(r1.w, Bm[7*12+j], s);
    s = fmaf(r2.x, Bm[8*12+j], s);
    s = fmaf(r2.y, Bm[9*12+j], s);
    s = fmaf(r2.z, Bm[10*12+j], s);
    return s;
}
__device__ __forceinline__ void storeP(float* C, int i, int j, float v){
    C[i*12+j] = v;
    if (j == 0) C[i*12+11] = 0.f;
}

// ---------------------------------------------------------------------------
// Kernel 1: emissions + numerator/emmax partials. Grid (NBLK, BB), 128 thr.
// ---------------------------------------------------------------------------
__global__ void __launch_bounds__(128) em_kernel(
    const float* __restrict__ seq,        // (B,T,4)
    const float* __restrict__ Wenc,       // (4,H)
    const float* __restrict__ benc,       // (H)
    const float* __restrict__ Wemit,      // (H,11)
    const float* __restrict__ bemit,      // (11)
    const float* __restrict__ start_tr,   // (11)
    const float* __restrict__ trans,      // (11,11)
    const float* __restrict__ end_tr,     // (11)
    const int* __restrict__ lengths,      // (B) int32
    const int* __restrict__ labels,       // (B,T) int32
    float* __restrict__ out)
{
    __shared__ float4 sEnc[HH];
    __shared__ float  sBenc[HH];
    __shared__ float4 sEmit[HH*3];
    __shared__ float  sRedN[4];
    __shared__ float  sRedD[4];

    int tid = threadIdx.x;
    int b = blockIdx.y;
    int t = blockIdx.x * 128 + tid;

    if (blockIdx.x == 0 && b == 0 && tid == 0) out[0] = 0.f;

    for (int i = tid; i < HH; i += 128) {
        sEnc[i]  = make_float4(Wenc[i], Wenc[HH+i], Wenc[2*HH+i], Wenc[3*HH+i]);
        sBenc[i] = benc[i];
        float e[12];
        #pragma unroll
        for (int c = 0; c < 11; c++) e[c] = Wemit[i*11 + c];
        e[11] = 0.f;
        sEmit[i*3+0] = make_float4(e[0], e[1], e[2],  e[3]);
        sEmit[i*3+1] = make_float4(e[4], e[5], e[6],  e[7]);
        sEmit[i*3+2] = make_float4(e[8], e[9], e[10], e[11]);
    }
    __syncthreads();

    float4 x = reinterpret_cast<const float4*>(seq)[(size_t)b*TT + t];

    float acc[11];
    #pragma unroll
    for (int c = 0; c < 11; c++) acc[c] = bemit[c];

    #pragma unroll 8
    for (int h = 0; h < HH; h++) {
        float4 w = sEnc[h];
        float hd = fmaxf(fmaf(x.x, w.x, fmaf(x.y, w.y, fmaf(x.z, w.z, fmaf(x.w, w.w, sBenc[h])))), 0.f);
        float4 e0 = sEmit[h*3+0], e1 = sEmit[h*3+1], e2 = sEmit[h*3+2];
        acc[0]  = fmaf(hd, e0.x, acc[0]);  acc[1]  = fmaf(hd, e0.y, acc[1]);
        acc[2]  = fmaf(hd, e0.z, acc[2]);  acc[3]  = fmaf(hd, e0.w, acc[3]);
        acc[4]  = fmaf(hd, e1.x, acc[4]);  acc[5]  = fmaf(hd, e1.y, acc[5]);
        acc[6]  = fmaf(hd, e1.z, acc[6]);  acc[7]  = fmaf(hd, e1.w, acc[7]);
        acc[8]  = fmaf(hd, e2.x, acc[8]);  acc[9]  = fmaf(hd, e2.y, acc[9]);
        acc[10] = fmaf(hd, e2.z, acc[10]);
    }

    float mx = acc[0];
    #pragma unroll
    for (int c = 1; c < 11; c++) mx = fmaxf(mx, acc[c]);
    float ee[12];
    #pragma unroll
    for (int c = 0; c < 11; c++) ee[c] = __expf(acc[c] - mx);
    ee[11] = mx;
    float4* dst = reinterpret_cast<float4*>(&g_eem[((size_t)b*TT + t) * 12]);
    dst[0] = make_float4(ee[0], ee[1], ee[2],  ee[3]);
    dst[1] = make_float4(ee[4], ee[5], ee[6],  ee[7]);
    dst[2] = make_float4(ee[8], ee[9], ee[10], ee[11]);

    int len = lengths[b];
    int lab = labels[(size_t)b*TT + t];
    int tag = (lab == -100) ? 0 : lab;
    float emtag = acc[0];
    #pragma unroll
    for (int c = 1; c < 11; c++) if (tag == c) emtag = acc[c];

    float contrib = 0.f;
    if (t == 0) {
        contrib = start_tr[tag] + emtag;
        float4* g4 = (float4*)&g_a0[b*12];
        g4[0] = make_float4(ee[0],ee[1],ee[2],ee[3]);
        g4[1] = make_float4(ee[4],ee[5],ee[6],ee[7]);
        g4[2] = make_float4(ee[8],ee[9],ee[10],0.f);
    } else if (t < len) {
        int labp = labels[(size_t)b*TT + t - 1];
        int tagp = (labp == -100) ? 0 : labp;
        contrib = trans[tagp*11 + tag] + emtag;
    }
    if (t == len - 1) contrib += end_tr[tag];

    float msk = (t < len) ? mx : 0.f;    // emmax sum over t<len (incl t=0)

    #pragma unroll
    for (int o = 16; o > 0; o >>= 1){
        contrib += __shfl_xor_sync(0xffffffffu, contrib, o);
        msk     += __shfl_xor_sync(0xffffffffu, msk, o);
    }
    if ((tid & 31) == 0){ sRedN[tid >> 5] = contrib; sRedD[tid >> 5] = msk; }
    __syncthreads();
    if (tid == 0){
        g_numpart[b*NBLK + blockIdx.x] = sRedN[0]+sRedN[1]+sRedN[2]+sRedN[3];
        g_denpart[b*NBLK + blockIdx.x] = sRedD[0]+sRedD[1]+sRedD[2]+sRedD[3];
    }
}

// ---------------------------------------------------------------------------
// Kernel 2: per-chunk serial transfer-matrix scan (proven). Grid (KCH,BB), 128.
// ---------------------------------------------------------------------------
__global__ void __launch_bounds__(128) chunk_kernel(
    const float* __restrict__ trans,
    const int* __restrict__ lengths)
{
    __shared__ float sEem[LCH*12];
    __shared__ float sM[2][MST];
    __shared__ float sRed[4];

    int tid = threadIdx.x;
    int c = blockIdx.x, b = blockIdx.y;
    int t0 = c * LCH;
    int len = lengths[b];

    {
        const float4* src = (const float4*)&g_eem[((size_t)b*TT + t0) * 12];
        for (int q = tid; q < LCH*3; q += 128) ((float4*)sEem)[q] = src[q];
    }

    int i = tid / 11, j = tid - i*11;
    bool act = tid < 121;
    float Tc[11];
    #pragma unroll
    for (int k = 0; k < 11; k++) Tc[k] = act ? __expf(trans[k*11 + j]) : 0.f;

    float v = (act && i == j) ? 1.f : 0.f;
    if (act){
        sM[0][i*12 + j] = v;
        if (j == 0){ sM[0][i*12 + 11] = 0.f; sM[1][i*12 + 11] = 0.f; }
    }
    int e_tot = 0;
    __syncthreads();

    int cur = 0;
    for (int s = 0; s < LCH; s++){
        int t = t0 + s;
        bool valid = (t >= 1) && (t < len);
        if (act && valid){
            const float4* row = (const float4*)&sM[cur][i*12];
            float4 r0 = row[0], r1 = row[1], r2 = row[2];
            float sum =      r0.x*Tc[0];
            sum = fmaf(r0.y, Tc[1], sum);
            sum = fmaf(r0.z, Tc[2], sum);
            sum = fmaf(r0.w, Tc[3], sum);
            sum = fmaf(r1.x, Tc[4], sum);
            sum = fmaf(r1.y, Tc[5], sum);
            sum = fmaf(r1.z, Tc[6], sum);
            sum = fmaf(r1.w, Tc[7], sum);
            sum = fmaf(r2.x, Tc[8], sum);
            sum = fmaf(r2.y, Tc[9], sum);
            sum = fmaf(r2.z, Tc[10], sum);
            v = sum * sEem[s*12 + j];
        }
        if ((s & 7) == 7){
            float m2 = v;
            #pragma unroll
            for (int o = 16; o > 0; o >>= 1) m2 = fmaxf(m2, __shfl_xor_sync(0xffffffffu, m2, o));
            if ((tid & 31) == 0) sRed[tid >> 5] = m2;
            __syncthreads();
            float mxv = fmaxf(fmaxf(sRed[0], sRed[1]), fmaxf(sRed[2], sRed[3]));
            int e = 0;
            frexpf(mxv, &e);
            v *= exp2f((float)(-e));
            e_tot += e;
        }
        if (act) sM[cur ^ 1][i*12 + j] = v;
        __syncthreads();
        cur ^= 1;
    }

    if (act){
        size_t base = ((size_t)(b*KCH + c)) * MST;
        g_M[base + i*12 + j] = v;
        if (j == 0) g_M[base + i*12 + 11] = 0.f;
    }
    if (tid == 0) g_exps[b*KCH + c] = e_tot;
}

// ---------------------------------------------------------------------------
// Kernel 3 (tail): per-batch full 7-level tree over 128 chunk matrices in
// SMEM (ping-pong; barriers only between levels) + partial sums + loss.
// Grid BB, 512 threads, 101 KB dynamic smem.
// ---------------------------------------------------------------------------
__global__ void __launch_bounds__(512) tail_kernel(
    const float* __restrict__ start_tr,
    const float* __restrict__ end_tr,
    float* __restrict__ out)
{
    extern __shared__ float dynsm[];
    float* bufA = dynsm;               // 128 matrices
    float* bufB = dynsm + 128*MST;     // 64 matrices
    __shared__ float sRedM[16];
    __shared__ float sNum, sDen;
    __shared__ int   sExp;

    int tid = threadIdx.x;
    int b = blockIdx.x;

    if (tid == 0){ sNum = 0.f; sDen = 0.f; sExp = 0; }
    __syncthreads();

    // load the batch's 128 chunk matrices
    {
        const float4* src = (const float4*)&g_M[(size_t)b*KCH*MST];
        for (int q = tid; q < 128*MST/4; q += 512) ((float4*)bufA)[q] = src[q];
    }

    // fold numerator / emmax / chunk-exponent partials
    {
        float nacc = 0.f, dacc = 0.f; int eacc = 0;
        if (tid < NBLK){ nacc = g_numpart[b*NBLK + tid]; dacc = g_denpart[b*NBLK + tid]; }
        if (tid < KCH)  eacc = g_exps[b*KCH + tid];
        #pragma unroll
        for (int o = 16; o > 0; o >>= 1){
            nacc += __shfl_xor_sync(0xffffffffu, nacc, o);
            dacc += __shfl_xor_sync(0xffffffffu, dacc, o);
            eacc += __shfl_xor_sync(0xffffffffu, eacc, o);
        }
        if ((tid & 31) == 0 && tid < KCH){
            atomicAdd(&sNum, nacc);
            atomicAdd(&sDen, dacc);
            atomicAdd(&sExp, eacc);
        }
    }
    __syncthreads();

    int unit = tid >> 7, st = tid & 127;
    int i = st / 11, j = st - i*11;
    bool act = st < 121;
    int wiu = st >> 5;

    // L1: 64 products, bufA -> bufB
    for (int q = unit; q < 64; q += 4)
        if (act) storeP(&bufB[q*MST], i, j, mm11(&bufA[(2*q)*MST], &bufA[(2*q+1)*MST], i, j));
    __syncthreads();
    // L2: 32, bufB -> bufA
    for (int q = unit; q < 32; q += 4)
        if (act) storeP(&bufA[q*MST], i, j, mm11(&bufB[(2*q)*MST], &bufB[(2*q+1)*MST], i, j));
    __syncthreads();
    // L3: 16, bufA -> bufB
    for (int q = unit; q < 16; q += 4)
        if (act) storeP(&bufB[q*MST], i, j, mm11(&bufA[(2*q)*MST], &bufA[(2*q+1)*MST], i, j));
    __syncthreads();
    // L4: 8 with pow2 norm, bufB -> bufA  (2 rounds)
    #pragma unroll
    for (int r = 0; r < 2; r++){
        int q = r*4 + unit;
        float v = act ? mm11(&bufB[(2*q)*MST], &bufB[(2*q+1)*MST], i, j) : 0.f;
        float m = v;
        #pragma unroll
        for (int o = 16; o > 0; o >>= 1) m = fmaxf(m, __shfl_xor_sync(0xffffffffu, m, o));
        if ((st & 31) == 0) sRedM[unit*4 + wiu] = m;
        __syncthreads();
        float mxv = fmaxf(fmaxf(sRedM[unit*4], sRedM[unit*4+1]), fmaxf(sRedM[unit*4+2], sRedM[unit*4+3]));
        int e = 0; frexpf(mxv, &e);
        if (act) storeP(&bufA[q*MST], i, j, v * exp2f((float)(-e)));
        if (st == 0) atomicAdd(&sExp, e);
        __syncthreads();
    }
    // L5: 4, bufA -> bufB
    {
        int q = unit;
        if (act) storeP(&bufB[q*MST], i, j, mm11(&bufA[(2*q)*MST], &bufA[(2*q+1)*MST], i, j));
    }
    __syncthreads();
    // L6: 2 with pow2 norm, bufB -> bufA (units 0,1)
    {
        bool run = unit < 2;
        float v = (run && act) ? mm11(&bufB[(2*unit)*MST], &bufB[(2*unit+1)*MST], i, j) : 0.f;
        float m = v;
        #pragma unroll
        for (int o = 16; o > 0; o >>= 1) m = fmaxf(m, __shfl_xor_sync(0xffffffffu, m, o));
        if ((st & 31) == 0) sRedM[unit*4 + wiu] = m;
        __syncthreads();
        float mxv = fmaxf(fmaxf(sRedM[unit*4], sRedM[unit*4+1]), fmaxf(sRedM[unit*4+2], sRedM[unit*4+3]));
        int e = 0; frexpf(mxv, &e);
        if (run && act) storeP(&bufA[unit*MST], i, j, v * exp2f((float)(-e)));
        if (run && st == 0) atomicAdd(&sExp, e);
        __syncthreads();
    }
    // L7: final product, bufA[0]*bufA[1] -> bufB[0]
    if (unit == 0 && act)
        storeP(&bufB[0], i, j, mm11(&bufA[0], &bufA[MST], i, j));
    __syncthreads();

    // final: loss
    if (tid < 32){
        bool a11 = tid < 11;
        float p0 = a11 ? __expf(start_tr[tid]) * g_a0[b*12 + tid] : 0.f;
        float pf = 0.f;
        #pragma unroll
        for (int k = 0; k < 11; k++){
            float pkv = __shfl_sync(0xffffffffu, p0, k);
            pf = fmaf(pkv, a11 ? bufB[k*12 + tid] : 0.f, pf);
        }
        float vv = a11 ? pf * __expf(end_tr[tid]) : 0.f;
        #pragma unroll
        for (int o = 16; o > 0; o >>= 1) vv += __shfl_xor_sync(0xffffffffu, vv, o);
        if (tid == 0){
            float den = logf(vv) + 0.6931471805599453f * (float)sExp + sDen;
            atomicAdd(out, (den - sNum) * (1.0f / (float)BB));
        }
    }
}

// ---------------------------------------------------------------------------
// Launch
// ---------------------------------------------------------------------------
#define SMEM_TAIL ((128*MST + 64*MST) * 4)

extern "C" void kernel_launch(void* const* d_in, const int* in_sizes, int n_in,
                              void* d_out, int out_size)
{
    const float* seq      = (const float*)d_in[0];
    const float* Wenc     = (const float*)d_in[1];
    const float* benc     = (const float*)d_in[2];
    const float* Wemit    = (const float*)d_in[3];
    const float* bemit    = (const float*)d_in[4];
    const float* start_tr = (const float*)d_in[5];
    const float* trans    = (const float*)d_in[6];
    const float* end_tr   = (const float*)d_in[7];
    const int* lengths    = (const int*)d_in[8];
    const int* labels     = (const int*)d_in[9];
    float* out = (float*)d_out;

    cudaFuncSetAttribute(tail_kernel, cudaFuncAttributeMaxDynamicSharedMemorySize, SMEM_TAIL);

    em_kernel<<<dim3(NBLK, BB), 128>>>(seq, Wenc, benc, Wemit, bemit,
                                       start_tr, trans, end_tr, lengths, labels, out);
    chunk_kernel<<<dim3(KCH, BB), 128>>>(trans, lengths);
    tail_kernel<<<BB, 512, SMEM_TAIL>>>(start_tr, end_tr, out);
}

// round 10
// speedup vs baseline: 1.6497x; 1.1496x over previous
#include <cuda_runtime.h>

#define BB 16
#define TT 8192
#define HH 256
#define LCH 64
#define KCH 128           // TT/LCH
#define MST 132           // matrix storage: 11 rows x 12 floats (padded)
#define NBLK 16           // em blocks per batch (TT/512)

typedef unsigned long long ull;

// Scratch (device globals — no allocation allowed)
__device__ __align__(16) float g_eem[(size_t)BB*TT*12];   // per token: ee[0..10], emmax
__device__ __align__(16) float g_M [(size_t)BB*KCH*MST];  // chunk transfer matrices
__device__ __align__(16) float g_a0[BB*12];               // ee at t=0 per batch
__device__ float g_numpart[BB*NBLK];                       // per-em-block numerator partials
__device__ float g_denpart[BB*NBLK];                       // per-em-block emmax-sum partials
__device__ int   g_exps[BB*KCH];                           // per-chunk pow2 exponents

// ---- packed f32x2 helpers (exact fp32 semantics) ----
__device__ __forceinline__ ull pk2(float lo, float hi){ ull r; asm("mov.b64 %0, {%1,%2};" : "=l"(r) : "f"(lo), "f"(hi)); return r; }
__device__ __forceinline__ void upk2(float &lo, float &hi, ull v){ asm("mov.b64 {%0,%1}, %2;" : "=f"(lo), "=f"(hi) : "l"(v)); }
__device__ __forceinline__ ull ffma2(ull a, ull b, ull c){ ull d; asm("fma.rn.f32x2 %0, %1, %2, %3;" : "=l"(d) : "l"(a), "l"(b), "l"(c)); return d; }

// C[i][j] = sum_k A[i][k]*B[k][j]; rows padded to 12 floats
__device__ __forceinline__ float mm11(const float* A, const float* Bm, int i, int j){
    float4 r0 = *(const float4*)&A[i*12];
    float4 r1 = *(const float4*)&A[i*12+4];
    float4 r2 = *(const float4*)&A[i*12+8];
    float s =        r0.x*Bm[0*12+j];
    s = fmaf(r0.y, Bm[1*12+j], s);
    s = fmaf(r0.z, Bm[2*12+j], s);
    s = fmaf(r0.w, Bm[3*12+j], s);
    s = fmaf(r1.x, Bm[4*12+j], s);
    s = fmaf(r1.y, Bm[5*12+j], s);
    s = fmaf(r1.z, Bm[6*12+j], s);
    s = fmaf(r1.w, Bm[7*12+j], s);
    s = fmaf(r2.x, Bm[8*12+j], s);
    s = fmaf(r2.y, Bm[9*12+j], s);
    s = fmaf(r2.z, Bm[10*12+j], s);
    return s;
}
__device__ __forceinline__ void storeP(float* C, int i, int j, float v){
    C[i*12+j] = v;
    if (j == 0) C[i*12+11] = 0.f;
}

// ---------------------------------------------------------------------------
// per-token epilogue: normalized exp-emissions + numerator contribution
// ---------------------------------------------------------------------------
__device__ __forceinline__ void process_token(
    int t, int b, int len,
    const float em[11],
    const float* __restrict__ start_tr, const float* __restrict__ trans,
    const float* __restrict__ end_tr, const int* __restrict__ labels,
    float& numc, float& msks)
{
    float mx = em[0];
    #pragma unroll
    for (int q = 1; q < 11; q++) mx = fmaxf(mx, em[q]);
    float ee[11];
    #pragma unroll
    for (int q = 0; q < 11; q++) ee[q] = __expf(em[q] - mx);

    float4* d4 = (float4*)&g_eem[((size_t)b*TT + t) * 12];
    d4[0] = make_float4(ee[0],ee[1],ee[2],ee[3]);
    d4[1] = make_float4(ee[4],ee[5],ee[6],ee[7]);
    d4[2] = make_float4(ee[8],ee[9],ee[10],mx);

    if (t < len) msks += mx;

    int lab = labels[(size_t)b*TT + t];
    int tag = (lab == -100) ? 0 : lab;
    float emt = em[0];
    #pragma unroll
    for (int q = 1; q < 11; q++) if (tag == q) emt = em[q];

    if (t == 0){
        numc += start_tr[tag] + emt;
        float4* g4 = (float4*)&g_a0[b*12];
        g4[0] = make_float4(ee[0],ee[1],ee[2],ee[3]);
        g4[1] = make_float4(ee[4],ee[5],ee[6],ee[7]);
        g4[2] = make_float4(ee[8],ee[9],ee[10],0.f);
    } else if (t < len){
        int labp = labels[(size_t)b*TT + t - 1];
        int tagp = (labp == -100) ? 0 : labp;
        numc += trans[tagp*11 + tag] + emt;
    }
    if (t == len - 1) numc += end_tr[tag];
}

// ---------------------------------------------------------------------------
// Kernel 1: emissions + numerator/emmax partials.
// Grid (NBLK, BB), 128 threads, 4 tokens per thread, f32x2 channel packing.
// ---------------------------------------------------------------------------
__global__ void __launch_bounds__(128) em_kernel(
    const float* __restrict__ seq,        // (B,T,4)
    const float* __restrict__ Wenc,       // (4,H)
    const float* __restrict__ benc,       // (H)
    const float* __restrict__ Wemit,      // (H,11)
    const float* __restrict__ bemit,      // (11)
    const float* __restrict__ start_tr,   // (11)
    const float* __restrict__ trans,      // (11,11)
    const float* __restrict__ end_tr,     // (11)
    const int* __restrict__ lengths,      // (B)
    const int* __restrict__ labels,       // (B,T)
    float* __restrict__ out)
{
    __shared__ float4     sEnc[HH];       // (w0,w1,w2,w3) per h
    __shared__ float      sBenc[HH];
    __shared__ ulonglong2 sEm[HH*2];      // [h*2+0]=(e01,e23), [h*2+1]=(e45,e67)
    __shared__ ull        sEm2[HH];       // (e8,e9)
    __shared__ ull        sEmX[HH];       // (e10,e10)
    __shared__ float      sRedN[4], sRedD[4];

    int tid = threadIdx.x;
    int b = blockIdx.y;
    int t0 = blockIdx.x * 512;
    int len = lengths[b];

    if (blockIdx.x == 0 && b == 0 && tid == 0) out[0] = 0.f;

    for (int h = tid; h < HH; h += 128){
        sEnc[h]  = make_float4(Wenc[h], Wenc[HH+h], Wenc[2*HH+h], Wenc[3*HH+h]);
        sBenc[h] = benc[h];
        float e[11];
        #pragma unroll
        for (int q = 0; q < 11; q++) e[q] = Wemit[h*11+q];
        sEm[h*2+0] = make_ulonglong2(pk2(e[0],e[1]), pk2(e[2],e[3]));
        sEm[h*2+1] = make_ulonglong2(pk2(e[4],e[5]), pk2(e[6],e[7]));
        sEm2[h] = pk2(e[8],e[9]);
        sEmX[h] = pk2(e[10],e[10]);
    }
    __syncthreads();

    // 4 tokens, interleaved for coalescing
    int ta = t0 + tid;                // +0,+128,+256,+384
    const float4* sq = (const float4*)seq + (size_t)b*TT;
    float4 x0 = sq[ta], x1 = sq[ta+128], x2 = sq[ta+256], x3 = sq[ta+384];

    ull b01 = pk2(bemit[0],bemit[1]);
    ull b23 = pk2(bemit[2],bemit[3]);
    ull b45 = pk2(bemit[4],bemit[5]);
    ull b67 = pk2(bemit[6],bemit[7]);
    ull b89 = pk2(bemit[8],bemit[9]);
    float b10 = bemit[10];

    ull a0[5] = {b01,b23,b45,b67,b89};
    ull a1[5] = {b01,b23,b45,b67,b89};
    ull a2[5] = {b01,b23,b45,b67,b89};
    ull a3[5] = {b01,b23,b45,b67,b89};
    ull aX01 = pk2(b10,b10), aX23 = pk2(b10,b10);

    #pragma unroll 2
    for (int h = 0; h < HH; h++){
        float4 w = sEnc[h];
        float bn = sBenc[h];
        ulonglong2 eA = sEm[h*2+0];
        ulonglong2 eB = sEm[h*2+1];
        ull e89 = sEm2[h];
        ull eXX = sEmX[h];

        float hd0 = fmaxf(fmaf(x0.x,w.x,fmaf(x0.y,w.y,fmaf(x0.z,w.z,fmaf(x0.w,w.w,bn)))), 0.f);
        float hd1 = fmaxf(fmaf(x1.x,w.x,fmaf(x1.y,w.y,fmaf(x1.z,w.z,fmaf(x1.w,w.w,bn)))), 0.f);
        float hd2 = fmaxf(fmaf(x2.x,w.x,fmaf(x2.y,w.y,fmaf(x2.z,w.z,fmaf(x2.w,w.w,bn)))), 0.f);
        float hd3 = fmaxf(fmaf(x3.x,w.x,fmaf(x3.y,w.y,fmaf(x3.z,w.z,fmaf(x3.w,w.w,bn)))), 0.f);

        ull p0 = pk2(hd0,hd0), p1 = pk2(hd1,hd1), p2 = pk2(hd2,hd2), p3 = pk2(hd3,hd3);

        a0[0]=ffma2(p0,eA.x,a0[0]); a0[1]=ffma2(p0,eA.y,a0[1]); a0[2]=ffma2(p0,eB.x,a0[2]); a0[3]=ffma2(p0,eB.y,a0[3]); a0[4]=ffma2(p0,e89,a0[4]);
        a1[0]=ffma2(p1,eA.x,a1[0]); a1[1]=ffma2(p1,eA.y,a1[1]); a1[2]=ffma2(p1,eB.x,a1[2]); a1[3]=ffma2(p1,eB.y,a1[3]); a1[4]=ffma2(p1,e89,a1[4]);
        a2[0]=ffma2(p2,eA.x,a2[0]); a2[1]=ffma2(p2,eA.y,a2[1]); a2[2]=ffma2(p2,eB.x,a2[2]); a2[3]=ffma2(p2,eB.y,a2[3]); a2[4]=ffma2(p2,e89,a2[4]);
        a3[0]=ffma2(p3,eA.x,a3[0]); a3[1]=ffma2(p3,eA.y,a3[1]); a3[2]=ffma2(p3,eB.x,a3[2]); a3[3]=ffma2(p3,eB.y,a3[3]); a3[4]=ffma2(p3,e89,a3[4]);

        aX01 = ffma2(pk2(hd0,hd1), eXX, aX01);
        aX23 = ffma2(pk2(hd2,hd3), eXX, aX23);
    }

    float x10a, x10b, x10c, x10d;
    upk2(x10a, x10b, aX01);
    upk2(x10c, x10d, aX23);

    float numc = 0.f, msks = 0.f;
    {
        float em[11];
        upk2(em[0],em[1],a0[0]); upk2(em[2],em[3],a0[1]); upk2(em[4],em[5],a0[2]);
        upk2(em[6],em[7],a0[3]); upk2(em[8],em[9],a0[4]); em[10]=x10a;
        process_token(ta, b, len, em, start_tr, trans, end_tr, labels, numc, msks);
    }
    {
        float em[11];
        upk2(em[0],em[1],a1[0]); upk2(em[2],em[3],a1[1]); upk2(em[4],em[5],a1[2]);
        upk2(em[6],em[7],a1[3]); upk2(em[8],em[9],a1[4]); em[10]=x10b;
        process_token(ta+128, b, len, em, start_tr, trans, end_tr, labels, numc, msks);
    }
    {
        float em[11];
        upk2(em[0],em[1],a2[0]); upk2(em[2],em[3],a2[1]); upk2(em[4],em[5],a2[2]);
        upk2(em[6],em[7],a2[3]); upk2(em[8],em[9],a2[4]); em[10]=x10c;
        process_token(ta+256, b, len, em, start_tr, trans, end_tr, labels, numc, msks);
    }
    {
        float em[11];
        upk2(em[0],em[1],a3[0]); upk2(em[2],em[3],a3[1]); upk2(em[4],em[5],a3[2]);
        upk2(em[6],em[7],a3[3]); upk2(em[8],em[9],a3[4]); em[10]=x10d;
        process_token(ta+384, b, len, em, start_tr, trans, end_tr, labels, numc, msks);
    }

    #pragma unroll
    for (int o = 16; o > 0; o >>= 1){
        numc += __shfl_xor_sync(0xffffffffu, numc, o);
        msks += __shfl_xor_sync(0xffffffffu, msks, o);
    }
    if ((tid & 31) == 0){ sRedN[tid >> 5] = numc; sRedD[tid >> 5] = msks; }
    __syncthreads();
    if (tid == 0){
        g_numpart[b*NBLK + blockIdx.x] = sRedN[0]+sRedN[1]+sRedN[2]+sRedN[3];
        g_denpart[b*NBLK + blockIdx.x] = sRedD[0]+sRedD[1]+sRedD[2]+sRedD[3];
    }
}

// ---------------------------------------------------------------------------
// Kernel 2: per-chunk serial transfer-matrix scan (proven). Grid (KCH,BB), 128.
// ---------------------------------------------------------------------------
__global__ void __launch_bounds__(128) chunk_kernel(
    const float* __restrict__ trans,
    const int* __restrict__ lengths)
{
    __shared__ float sEem[LCH*12];
    __shared__ float sM[2][MST];
    __shared__ float sRed[4];

    int tid = threadIdx.x;
    int c = blockIdx.x, b = blockIdx.y;
    int t0 = c * LCH;
    int len = lengths[b];

    {
        const float4* src = (const float4*)&g_eem[((size_t)b*TT + t0) * 12];
        for (int q = tid; q < LCH*3; q += 128) ((float4*)sEem)[q] = src[q];
    }

    int i = tid / 11, j = tid - i*11;
    bool act = tid < 121;
    float Tc[11];
    #pragma unroll
    for (int k = 0; k < 11; k++) Tc[k] = act ? __expf(trans[k*11 + j]) : 0.f;

    float v = (act && i == j) ? 1.f : 0.f;
    if (act){
        sM[0][i*12 + j] = v;
        if (j == 0){ sM[0][i*12 + 11] = 0.f; sM[1][i*12 + 11] = 0.f; }
    }
    int e_tot = 0;
    __syncthreads();

    int cur = 0;
    for (int s = 0; s < LCH; s++){
        int t = t0 + s;
        bool valid = (t >= 1) && (t < len);
        if (act && valid){
            const float4* row = (const float4*)&sM[cur][i*12];
            float4 r0 = row[0], r1 = row[1], r2 = row[2];
            float sum =      r0.x*Tc[0];
            sum = fmaf(r0.y, Tc[1], sum);
            sum = fmaf(r0.z, Tc[2], sum);
            sum = fmaf(r0.w, Tc[3], sum);
            sum = fmaf(r1.x, Tc[4], sum);
            sum = fmaf(r1.y, Tc[5], sum);
            sum = fmaf(r1.z, Tc[6], sum);
            sum = fmaf(r1.w, Tc[7], sum);
            sum = fmaf(r2.x, Tc[8], sum);
            sum = fmaf(r2.y, Tc[9], sum);
            sum = fmaf(r2.z, Tc[10], sum);
            v = sum * sEem[s*12 + j];
        }
        if ((s & 7) == 7){
            float m2 = v;
            #pragma unroll
            for (int o = 16; o > 0; o >>= 1) m2 = fmaxf(m2, __shfl_xor_sync(0xffffffffu, m2, o));
            if ((tid & 31) == 0) sRed[tid >> 5] = m2;
            __syncthreads();
            float mxv = fmaxf(fmaxf(sRed[0], sRed[1]), fmaxf(sRed[2], sRed[3]));
            int e = 0;
            frexpf(mxv, &e);
            v *= exp2f((float)(-e));
            e_tot += e;
        }
        if (act) sM[cur ^ 1][i*12 + j] = v;
        __syncthreads();
        cur ^= 1;
    }

    if (act){
        size_t base = ((size_t)(b*KCH + c)) * MST;
        g_M[base + i*12 + j] = v;
        if (j == 0) g_M[base + i*12 + 11] = 0.f;
    }
    if (tid == 0) g_exps[b*KCH + c] = e_tot;
}

// ---------------------------------------------------------------------------
// Kernel 3 (tail): per-batch full 7-level tree over 128 chunk matrices in
// SMEM (ping-pong; barriers only between levels) + partial sums + loss.
// Grid BB, 512 threads, 101 KB dynamic smem.
// ---------------------------------------------------------------------------
__global__ void __launch_bounds__(512) tail_kernel(
    const float* __restrict__ start_tr,
    const float* __restrict__ end_tr,
    float* __restrict__ out)
{
    extern __shared__ float dynsm[];
    float* bufA = dynsm;               // 128 matrices
    float* bufB = dynsm + 128*MST;     // 64 matrices
    __shared__ float sRedM[16];
    __shared__ float sNum, sDen;
    __shared__ int   sExp;

    int tid = threadIdx.x;
    int b = blockIdx.x;

    if (tid == 0){ sNum = 0.f; sDen = 0.f; sExp = 0; }
    __syncthreads();

    {
        const float4* src = (const float4*)&g_M[(size_t)b*KCH*MST];
        for (int q = tid; q < 128*MST/4; q += 512) ((float4*)bufA)[q] = src[q];
    }

    {
        float nacc = 0.f, dacc = 0.f; int eacc = 0;
        if (tid < NBLK){ nacc = g_numpart[b*NBLK + tid]; dacc = g_denpart[b*NBLK + tid]; }
        if (tid < KCH)  eacc = g_exps[b*KCH + tid];
        #pragma unroll
        for (int o = 16; o > 0; o >>= 1){
            nacc += __shfl_xor_sync(0xffffffffu, nacc, o);
            dacc += __shfl_xor_sync(0xffffffffu, dacc, o);
            eacc += __shfl_xor_sync(0xffffffffu, eacc, o);
        }
        if ((tid & 31) == 0 && tid < KCH){
            atomicAdd(&sNum, nacc);
            atomicAdd(&sDen, dacc);
            atomicAdd(&sExp, eacc);
        }
    }
    __syncthreads();

    int unit = tid >> 7, st = tid & 127;
    int i = st / 11, j = st - i*11;
    bool act = st < 121;
    int wiu = st >> 5;

    // L1: 64 products, bufA -> bufB
    for (int q = unit; q < 64; q += 4)
        if (act) storeP(&bufB[q*MST], i, j, mm11(&bufA[(2*q)*MST], &bufA[(2*q+1)*MST], i, j));
    __syncthreads();
    // L2: 32, bufB -> bufA
    for (int q = unit; q < 32; q += 4)
        if (act) storeP(&bufA[q*MST], i, j, mm11(&bufB[(2*q)*MST], &bufB[(2*q+1)*MST], i, j));
    __syncthreads();
    // L3: 16, bufA -> bufB
    for (int q = unit; q < 16; q += 4)
        if (act) storeP(&bufB[q*MST], i, j, mm11(&bufA[(2*q)*MST], &bufA[(2*q+1)*MST], i, j));
    __syncthreads();
    // L4: 8 with pow2 norm, bufB -> bufA  (2 rounds)
    #pragma unroll
    for (int r = 0; r < 2; r++){
        int q = r*4 + unit;
        float v = act ? mm11(&bufB[(2*q)*MST], &bufB[(2*q+1)*MST], i, j) : 0.f;
        float m = v;
        #pragma unroll
        for (int o = 16; o > 0; o >>= 1) m = fmaxf(m, __shfl_xor_sync(0xffffffffu, m, o));
        if ((st & 31) == 0) sRedM[unit*4 + wiu] = m;
        __syncthreads();
        float mxv = fmaxf(fmaxf(sRedM[unit*4], sRedM[unit*4+1]), fmaxf(sRedM[unit*4+2], sRedM[unit*4+3]));
        int e = 0; frexpf(mxv, &e);
        if (act) storeP(&bufA[q*MST], i, j, v * exp2f((float)(-e)));
        if (st == 0) atomicAdd(&sExp, e);
        __syncthreads();
    }
    // L5: 4, bufA -> bufB
    {
        int q = unit;
        if (act) storeP(&bufB[q*MST], i, j, mm11(&bufA[(2*q)*MST], &bufA[(2*q+1)*MST], i, j));
    }
    __syncthreads();
    // L6: 2 with pow2 norm, bufB -> bufA (units 0,1)
    {
        bool run = unit < 2;
        float v = (run && act) ? mm11(&bufB[(2*unit)*MST], &bufB[(2*unit+1)*MST], i, j) : 0.f;
        float m = v;
        #pragma unroll
        for (int o = 16; o > 0; o >>= 1) m = fmaxf(m, __shfl_xor_sync(0xffffffffu, m, o));
        if ((st & 31) == 0) sRedM[unit*4 + wiu] = m;
        __syncthreads();
        float mxv = fmaxf(fmaxf(sRedM[unit*4], sRedM[unit*4+1]), fmaxf(sRedM[unit*4+2], sRedM[unit*4+3]));
        int e = 0; frexpf(mxv, &e);
        if (run && act) storeP(&bufA[unit*MST], i, j, v * exp2f((float)(-e)));
        if (run && st == 0) atomicAdd(&sExp, e);
        __syncthreads();
    }
    // L7: final product, bufA[0]*bufA[1] -> bufB[0]
    if (unit == 0 && act)
        storeP(&bufB[0], i, j, mm11(&bufA[0], &bufA[MST], i, j));
    __syncthreads();

    if (tid < 32){
        bool a11 = tid < 11;
        float p0 = a11 ? __expf(start_tr[tid]) * g_a0[b*12 + tid] : 0.f;
        float pf = 0.f;
        #pragma unroll
        for (int k = 0; k < 11; k++){
            float pkv = __shfl_sync(0xffffffffu, p0, k);
            pf = fmaf(pkv, a11 ? bufB[k*12 + tid] : 0.f, pf);
        }
        float vv = a11 ? pf * __expf(end_tr[tid]) : 0.f;
        #pragma unroll
        for (int o = 16; o > 0; o >>= 1) vv += __shfl_xor_sync(0xffffffffu, vv, o);
        if (tid == 0){
            float den = logf(vv) + 0.6931471805599453f * (float)sExp + sDen;
            atomicAdd(out, (den - sNum) * (1.0f / (float)BB));
        }
    }
}

// ---------------------------------------------------------------------------
// Launch
// ---------------------------------------------------------------------------
#define SMEM_TAIL ((128*MST + 64*MST) * 4)

extern "C" void kernel_launch(void* const* d_in, const int* in_sizes, int n_in,
                              void* d_out, int out_size)
{
    const float* seq      = (const float*)d_in[0];
    const float* Wenc     = (const float*)d_in[1];
    const float* benc     = (const float*)d_in[2];
    const float* Wemit    = (const float*)d_in[3];
    const float* bemit    = (const float*)d_in[4];
    const float* start_tr = (const float*)d_in[5];
    const float* trans    = (const float*)d_in[6];
    const float* end_tr   = (const float*)d_in[7];
    const int* lengths    = (const int*)d_in[8];
    const int* labels     = (const int*)d_in[9];
    float* out = (float*)d_out;

    cudaFuncSetAttribute(tail_kernel, cudaFuncAttributeMaxDynamicSharedMemorySize, SMEM_TAIL);

    em_kernel<<<dim3(NBLK, BB), 128>>>(seq, Wenc, benc, Wemit, bemit,
                                       start_tr, trans, end_tr, lengths, labels, out);
    chunk_kernel<<<dim3(KCH, BB), 128>>>(trans, lengths);
    tail_kernel<<<BB, 512, SMEM_TAIL>>>(start_tr, end_tr, out);
}